// round 7
// baseline (speedup 1.0000x reference)
#include <cuda_runtime.h>
#include <cuda_bf16.h>

#define N_BATCH 4096
#define T_SEQ   200
#define PADK    10
#define WCH     4096          // floats per weight chunk (16 KB)

// ---------------- device scratch (no allocs allowed) ----------------
// wt1[k*512 + jg*4 + jj] = W1[(jg + 128*jj)*128 + k]   (k<128, jg<128, jj<4)
__device__ float g_wt1[128 * 512];
// wt2[k*256 + jg*2 + jj] = W2[(jg + 128*jj)*512 + k]   (k<512, jg<128, jj<2)
__device__ float g_wt2[512 * 256];
// wt3[k*128 + j]         = W3[j*256 + k]               (k<256, j<128)
__device__ float g_wt3[256 * 128];

// ---------------- f32x2 helpers (sm_103a packed fp32) ----------------
typedef unsigned long long u64;

__device__ __forceinline__ u64 pk2(float lo, float hi) {
    u64 r; asm("mov.b64 %0, {%1,%2};" : "=l"(r) : "f"(lo), "f"(hi)); return r;
}
__device__ __forceinline__ float2 upk(u64 v) {
    float2 f; asm("mov.b64 {%0,%1}, %2;" : "=f"(f.x), "=f"(f.y) : "l"(v)); return f;
}
__device__ __forceinline__ void fma2(u64& d, u64 a, u64 b) {
    asm("fma.rn.f32x2 %0, %1, %2, %0;" : "+l"(d) : "l"(a), "l"(b));
}

// ---------------- cp.async helpers ----------------
__device__ __forceinline__ void cp16(unsigned int dst, const float* src) {
    asm volatile("cp.async.ca.shared.global [%0], [%1], 16;\n" :: "r"(dst), "l"(src));
}
__device__ __forceinline__ void cp_commit() {
    asm volatile("cp.async.commit_group;\n");
}
template<int N> __device__ __forceinline__ void cp_wait() {
    asm volatile("cp.async.wait_group %0;\n" :: "n"(N));
}

// ---------------- 1) weight transpose (coalesced reads) ----------------
__global__ void transpose_kernel(const float* __restrict__ W1,
                                 const float* __restrict__ W2,
                                 const float* __restrict__ W3) {
    int idx = blockIdx.x * blockDim.x + threadIdx.x;
    if (idx < 65536) {                         // W1: 512x128 (j*128+k)
        int j = idx >> 7, k = idx & 127;
        int jg = j & 127, jj = j >> 7;
        g_wt1[k * 512 + jg * 4 + jj] = W1[idx];
    } else if (idx < 65536 + 131072) {         // W2: 256x512 (j*512+k)
        int i2 = idx - 65536;
        int j = i2 >> 9, k = i2 & 511;
        int jg = j & 127, jj = j >> 7;
        g_wt2[k * 256 + jg * 2 + jj] = W2[i2];
    } else if (idx < 65536 + 131072 + 32768) { // W3: 128x256 (j*256+k)
        int i3 = idx - 65536 - 131072;
        int j = i3 >> 8, k = i3 & 255;
        g_wt3[k * 128 + j] = W3[i3];
    }
}

// ---------------- 2) fused pool + MLP: 16 rows/block, 512 threads ----------------
// Activation u64 word = (row 2p, row 2p+1), layout [k][pair] with PADK=10 padding.
// Weights streamed via triple-buffered cp.async staging (3 x 16 KB).
__global__ void __launch_bounds__(512, 2) mlp_kernel(
        const int*   __restrict__ x,
        const int*   __restrict__ lengths,
        const float* __restrict__ emb,
        const float* __restrict__ b1,
        const float* __restrict__ b2,
        const float* __restrict__ b3,
        const float* __restrict__ W4,
        const float* __restrict__ b4,
        float* __restrict__ out) {
    __shared__ __align__(16) u64   S[512 * PADK + 256 * PADK];   // 60 KB activations
    __shared__ __align__(16) float WS[3][WCH];                   // 48 KB weight stage
    u64* A1  = S;                      // [k*PADK + p], k<512
    u64* B2  = S + 512 * PADK;         // [k*PADK + p], k<256
    u64* BIN = B2;                     // [k*PADK + p], k<128 (dead after layer 1)
    u64* A3  = A1;                     // [j*PADK + p], j<128 (layer 3 out)

    int tid   = threadIdx.x;
    int w     = tid >> 5;              // warp 0..15
    int lane  = tid & 31;
    int jg    = tid & 127;             // output-group index
    int pbase = (tid >> 7) * 2;        // pair base: 0,2,4,6 (uniform per warp)
    int r0    = blockIdx.x * 16;

    unsigned int wsbase = (unsigned int)__cvta_generic_to_shared(&WS[0][0]);
    // stage chunk (4096 floats) from gsrc into buffer buf
    auto stage = [&](int buf, const float* gsrc) {
        unsigned int d = wsbase + buf * (WCH * 4) + tid * 16;
        const float* g = gsrc + tid * 4;
        cp16(d, g);
        cp16(d + 8192, g + 2048);
    };

    // ---- pooling: warp w pools row r0+w ----
    {
        int row = r0 + w;
        const int* xr = x + row * T_SEQ;
        int len = lengths[row];
        const float4* emb4 = (const float4*)emb;
        float4 acc = make_float4(0.f, 0.f, 0.f, 0.f);
        int t = 0;
        for (; t + 8 <= len; t += 8) {
            int4 ia = *(const int4*)(xr + t);
            int4 ib = *(const int4*)(xr + t + 4);
            float4 v0 = emb4[ia.x * 32 + lane];
            float4 v1 = emb4[ia.y * 32 + lane];
            float4 v2 = emb4[ia.z * 32 + lane];
            float4 v3 = emb4[ia.w * 32 + lane];
            float4 v4 = emb4[ib.x * 32 + lane];
            float4 v5 = emb4[ib.y * 32 + lane];
            float4 v6 = emb4[ib.z * 32 + lane];
            float4 v7 = emb4[ib.w * 32 + lane];
            acc.x += ((v0.x + v1.x) + (v2.x + v3.x)) + ((v4.x + v5.x) + (v6.x + v7.x));
            acc.y += ((v0.y + v1.y) + (v2.y + v3.y)) + ((v4.y + v5.y) + (v6.y + v7.y));
            acc.z += ((v0.z + v1.z) + (v2.z + v3.z)) + ((v4.z + v5.z) + (v6.z + v7.z));
            acc.w += ((v0.w + v1.w) + (v2.w + v3.w)) + ((v4.w + v5.w) + (v6.w + v7.w));
        }
        for (; t < len; ++t) {
            float4 a = emb4[xr[t] * 32 + lane];
            acc.x += a.x; acc.y += a.y; acc.z += a.z; acc.w += a.w;
        }
        float inv = 1.0f / (float)len;
        acc.x *= inv; acc.y *= inv; acc.z *= inv; acc.w *= inv;

        float* Bf = (float*)BIN;                 // pair p = w>>1, half s = w&1
        int p = w >> 1, s = w & 1;
        Bf[((4 * lane + 0) * PADK + p) * 2 + s] = acc.x;
        Bf[((4 * lane + 1) * PADK + p) * 2 + s] = acc.y;
        Bf[((4 * lane + 2) * PADK + p) * 2 + s] = acc.z;
        Bf[((4 * lane + 3) * PADK + p) * 2 + s] = acc.w;
    }
    __syncthreads();

    // ---- layer 1: 128 -> 512 (16 chunks of 8 k) ----
    {
        u64 acc[4][2];
        #pragma unroll
        for (int jj = 0; jj < 4; ++jj) { acc[jj][0] = 0ULL; acc[jj][1] = 0ULL; }

        stage(0, g_wt1);          cp_commit();
        stage(1, g_wt1 + WCH);    cp_commit();
        for (int c = 0; c < 16; ++c) {
            cp_wait<1>();
            __syncthreads();
            const float4* wb = (const float4*)WS[c % 3];
            const u64* bp = BIN + (c * 8) * PADK + pbase;
            #pragma unroll
            for (int kk = 0; kk < 8; ++kk) {
                float4 wv = wb[kk * 128 + jg];                      // LDS.128, cf
                ulonglong2 ap = *(const ulonglong2*)(bp + kk * PADK); // uniform LDS.128
                u64 w0 = pk2(wv.x, wv.x), w1 = pk2(wv.y, wv.y);
                u64 w2 = pk2(wv.z, wv.z), w3 = pk2(wv.w, wv.w);
                fma2(acc[0][0], ap.x, w0); fma2(acc[0][1], ap.y, w0);
                fma2(acc[1][0], ap.x, w1); fma2(acc[1][1], ap.y, w1);
                fma2(acc[2][0], ap.x, w2); fma2(acc[2][1], ap.y, w2);
                fma2(acc[3][0], ap.x, w3); fma2(acc[3][1], ap.y, w3);
            }
            if (c + 2 < 16) stage((c + 2) % 3, g_wt1 + (c + 2) * WCH);
            cp_commit();
        }
        __syncthreads();   // all BIN reads done; B2 region reusable
        #pragma unroll
        for (int jj = 0; jj < 4; ++jj) {
            int n1 = jg + 128 * jj;
            float bj = b1[n1];
            float2 v0 = upk(acc[jj][0]);
            float2 v1 = upk(acc[jj][1]);
            ulonglong2 st;
            st.x = pk2(fmaxf(v0.x + bj, 0.f), fmaxf(v0.y + bj, 0.f));
            st.y = pk2(fmaxf(v1.x + bj, 0.f), fmaxf(v1.y + bj, 0.f));
            *(ulonglong2*)(A1 + n1 * PADK + pbase) = st;
        }
    }
    __syncthreads();

    // ---- layer 2: 512 -> 256 (32 chunks of 16 k) ----
    {
        u64 acc[2][2];
        acc[0][0] = acc[0][1] = acc[1][0] = acc[1][1] = 0ULL;

        stage(0, g_wt2);          cp_commit();
        stage(1, g_wt2 + WCH);    cp_commit();
        for (int c = 0; c < 32; ++c) {
            cp_wait<1>();
            __syncthreads();
            const float2* wb = (const float2*)WS[c % 3];
            const u64* apb = A1 + (c * 16) * PADK + pbase;
            #pragma unroll
            for (int kk = 0; kk < 16; ++kk) {
                float2 wv = wb[kk * 128 + jg];                        // LDS.64, cf
                ulonglong2 ap = *(const ulonglong2*)(apb + kk * PADK);  // uniform LDS.128
                u64 w0 = pk2(wv.x, wv.x), w1 = pk2(wv.y, wv.y);
                fma2(acc[0][0], ap.x, w0); fma2(acc[0][1], ap.y, w0);
                fma2(acc[1][0], ap.x, w1); fma2(acc[1][1], ap.y, w1);
            }
            if (c + 2 < 32) stage((c + 2) % 3, g_wt2 + (c + 2) * WCH);
            cp_commit();
        }
        #pragma unroll
        for (int jj = 0; jj < 2; ++jj) {
            int j = jg + 128 * jj;
            float bj = b2[j];
            float2 v0 = upk(acc[jj][0]);
            float2 v1 = upk(acc[jj][1]);
            ulonglong2 st;
            st.x = pk2(fmaxf(v0.x + bj, 0.f), fmaxf(v0.y + bj, 0.f));
            st.y = pk2(fmaxf(v1.x + bj, 0.f), fmaxf(v1.y + bj, 0.f));
            *(ulonglong2*)(B2 + j * PADK + pbase) = st;   // BIN dead; safe
        }
    }
    __syncthreads();

    // ---- layer 3: 256 -> 128 (8 chunks of 32 k) ----
    {
        u64 acc0 = 0ULL, acc1 = 0ULL;

        stage(0, g_wt3);          cp_commit();
        stage(1, g_wt3 + WCH);    cp_commit();
        for (int c = 0; c < 8; ++c) {
            cp_wait<1>();
            __syncthreads();
            const float* wb = WS[c % 3];
            const u64* bpb = B2 + (c * 32) * PADK + pbase;
            #pragma unroll
            for (int kk = 0; kk < 32; ++kk) {
                float wv = wb[kk * 128 + jg];                         // LDS.32, cf
                ulonglong2 ap = *(const ulonglong2*)(bpb + kk * PADK);  // uniform LDS.128
                u64 ws = pk2(wv, wv);
                fma2(acc0, ap.x, ws); fma2(acc1, ap.y, ws);
            }
            if (c + 2 < 8) stage((c + 2) % 3, g_wt3 + (c + 2) * WCH);
            cp_commit();
        }
        __syncthreads();   // A1 reads (layer 2) long done; A3 overlap safe
        float bj = b3[jg];
        float2 v0 = upk(acc0);
        float2 v1 = upk(acc1);
        ulonglong2 st;
        st.x = pk2(fmaxf(v0.x + bj, 0.f), fmaxf(v0.y + bj, 0.f));
        st.y = pk2(fmaxf(v1.x + bj, 0.f), fmaxf(v1.y + bj, 0.f));
        *(ulonglong2*)(A3 + jg * PADK + pbase) = st;
    }
    __syncthreads();

    // ---- layer 4: 128 -> 2 (one warp: r = tid>>1, jo = tid&1) ----
    if (tid < 32) {
        int r  = tid >> 1;             // 0..15
        int jo = tid & 1;
        int p = r >> 1, h = r & 1;
        float acc = b4[jo];
        #pragma unroll 8
        for (int k = 0; k < 128; ++k) {
            float2 v = upk(A3[k * PADK + p]);
            acc += (h ? v.y : v.x) * W4[jo * 128 + k];
        }
        out[(r0 + r) * 2 + jo] = acc;
    }
}

// ---------------- launch ----------------
extern "C" void kernel_launch(void* const* d_in, const int* in_sizes, int n_in,
                              void* d_out, int out_size) {
    const int*   x       = (const int*)  d_in[0];
    const int*   lengths = (const int*)  d_in[1];
    const float* emb     = (const float*)d_in[2];
    const float* W1      = (const float*)d_in[3];
    const float* b1      = (const float*)d_in[4];
    const float* W2      = (const float*)d_in[5];
    const float* b2      = (const float*)d_in[6];
    const float* W3      = (const float*)d_in[7];
    const float* b3      = (const float*)d_in[8];
    const float* W4      = (const float*)d_in[9];
    const float* b4      = (const float*)d_in[10];
    float* out = (float*)d_out;

    transpose_kernel<<<(229376 + 255) / 256, 256>>>(W1, W2, W3);
    mlp_kernel<<<N_BATCH / 16, 512>>>(x, lengths, emb, b1, b2, b3, W4, b4, out);
}

// round 8
// speedup vs baseline: 1.0515x; 1.0515x over previous
#include <cuda_runtime.h>
#include <cuda_bf16.h>

#define N_BATCH 4096
#define T_SEQ   200
#define PADR    18          // u64 words per k-pair row-slot (16 rows + 2 pad)

// ---------------- device scratch (no allocs allowed) ----------------
// k-pair interleaved transposed weights:
// wt1[(k>>1)*1024 + j*2 + (k&1)] = W1[j*128 + k]   (k<128, j<512)
__device__ float g_wt1[128 * 512];
// wt2[(k>>1)*512  + j*2 + (k&1)] = W2[j*512 + k]   (k<512, j<256)
__device__ float g_wt2[512 * 256];
// wt3[(k>>1)*256  + j*2 + (k&1)] = W3[j*256 + k]   (k<256, j<128)
__device__ float g_wt3[256 * 128];

// ---------------- f32x2 helpers (sm_103a packed fp32) ----------------
typedef unsigned long long u64;

__device__ __forceinline__ float2 upk(u64 v) {
    float2 f; asm("mov.b64 {%0,%1}, %2;" : "=f"(f.x), "=f"(f.y) : "l"(v)); return f;
}
__device__ __forceinline__ void fma2(u64& d, u64 a, u64 b) {
    asm("fma.rn.f32x2 %0, %1, %2, %0;" : "+l"(d) : "l"(a), "l"(b));
}

// ---------------- 1) weight transpose (coalesced reads) ----------------
__global__ void transpose_kernel(const float* __restrict__ W1,
                                 const float* __restrict__ W2,
                                 const float* __restrict__ W3) {
    int idx = blockIdx.x * blockDim.x + threadIdx.x;
    if (idx < 65536) {                         // W1: 512x128 (j*128+k)
        int j = idx >> 7, k = idx & 127;
        g_wt1[(k >> 1) * 1024 + j * 2 + (k & 1)] = W1[idx];
    } else if (idx < 65536 + 131072) {         // W2: 256x512 (j*512+k)
        int i2 = idx - 65536;
        int j = i2 >> 9, k = i2 & 511;
        g_wt2[(k >> 1) * 512 + j * 2 + (k & 1)] = W2[i2];
    } else if (idx < 65536 + 131072 + 32768) { // W3: 128x256 (j*256+k)
        int i3 = idx - 65536 - 131072;
        int j = i3 >> 8, k = i3 & 255;
        g_wt3[(k >> 1) * 256 + j * 2 + (k & 1)] = W3[i3];
    }
}

// ---------------- 2) fused pool + MLP: 16 rows per block, 512 threads ----------------
// Activation u64 word at [(k>>1)*PADR + r] = (a_r[k_even], a_r[k_odd]).
// Accumulators are (even-k partial, odd-k partial); one FADD merge per layer end.
// Smem:
//   A1 = S        : 256 kp * PADR u64 (36 KB)  layer1 out; tail reused as A3 (scalar)
//   B2 = S + 4608 : 128 kp * PADR u64 (18 KB)  layer2 out; overlays BIN (pooled in, 64 kp)
__global__ void __launch_bounds__(512, 2) mlp_kernel(
        const int*   __restrict__ x,
        const int*   __restrict__ lengths,
        const float* __restrict__ emb,
        const float* __restrict__ b1,
        const float* __restrict__ b2,
        const float* __restrict__ b3,
        const float* __restrict__ W4,
        const float* __restrict__ b4,
        float* __restrict__ out) {
    __shared__ __align__(16) u64 S[256 * PADR + 128 * PADR];   // 54 KB
    u64* A1  = S;                       // [kp*PADR + r], kp<256
    u64* B2  = S + 256 * PADR;          // [kp*PADR + r], kp<128
    u64* BIN = B2;                      // [kp*PADR + r], kp<64 (dead after layer 1)
    float* A3f = (float*)A1;            // [j*16 + r], j<128 (layer 3 out, scalar)

    int tid  = threadIdx.x;
    int w    = tid >> 5;                // warp 0..15 == row within block
    int lane = tid & 31;
    int r0   = blockIdx.x * 16;

    // ---- pooling: warp w pools row r0+w ----
    {
        int row = r0 + w;
        const int* xr = x + row * T_SEQ;
        int len = lengths[row];
        const float4* emb4 = (const float4*)emb;
        float4 acc = make_float4(0.f, 0.f, 0.f, 0.f);
        int t = 0;
        for (; t + 8 <= len; t += 8) {
            int4 ia = *(const int4*)(xr + t);
            int4 ib = *(const int4*)(xr + t + 4);
            float4 v0 = emb4[ia.x * 32 + lane];
            float4 v1 = emb4[ia.y * 32 + lane];
            float4 v2 = emb4[ia.z * 32 + lane];
            float4 v3 = emb4[ia.w * 32 + lane];
            float4 v4 = emb4[ib.x * 32 + lane];
            float4 v5 = emb4[ib.y * 32 + lane];
            float4 v6 = emb4[ib.z * 32 + lane];
            float4 v7 = emb4[ib.w * 32 + lane];
            acc.x += ((v0.x + v1.x) + (v2.x + v3.x)) + ((v4.x + v5.x) + (v6.x + v7.x));
            acc.y += ((v0.y + v1.y) + (v2.y + v3.y)) + ((v4.y + v5.y) + (v6.y + v7.y));
            acc.z += ((v0.z + v1.z) + (v2.z + v3.z)) + ((v4.z + v5.z) + (v6.z + v7.z));
            acc.w += ((v0.w + v1.w) + (v2.w + v3.w)) + ((v4.w + v5.w) + (v6.w + v7.w));
        }
        for (; t < len; ++t) {
            float4 a = emb4[xr[t] * 32 + lane];
            acc.x += a.x; acc.y += a.y; acc.z += a.z; acc.w += a.w;
        }
        float inv = 1.0f / (float)len;
        acc.x *= inv; acc.y *= inv; acc.z *= inv; acc.w *= inv;

        // lane owns k = 4*lane..4*lane+3 -> k-pairs kp = 2*lane, 2*lane+1
        float2* Bf2 = (float2*)BIN;
        Bf2[(2 * lane + 0) * PADR + w] = make_float2(acc.x, acc.y);
        Bf2[(2 * lane + 1) * PADR + w] = make_float2(acc.z, acc.w);
    }
    __syncthreads();

    // ---- layer 1: 128 -> 512; thread j = tid, all 16 rows ----
    {
        int j = tid;
        u64 acc[16];
        #pragma unroll
        for (int r = 0; r < 16; ++r) acc[r] = 0ULL;

        const u64* Wt = (const u64*)g_wt1;     // [kp*512 + j]
        #pragma unroll 2
        for (int kp = 0; kp < 64; ++kp) {
            u64 w2 = Wt[kp * 512 + j];         // LDG.64, coalesced, no dup
            const u64* bp = BIN + kp * PADR;
            #pragma unroll
            for (int q = 0; q < 8; ++q) {
                ulonglong2 ap = *(const ulonglong2*)(bp + 2 * q);  // uniform LDS.128
                fma2(acc[2 * q],     ap.x, w2);
                fma2(acc[2 * q + 1], ap.y, w2);
            }
        }
        __syncthreads();   // all BIN reads done; B2 region reusable
        float bj = b1[j];
        float* A1f = (float*)A1;
        int base = ((j >> 1) * PADR) * 2 + (j & 1);   // float index, stride 2 per row
        #pragma unroll
        for (int r = 0; r < 16; ++r) {
            float2 v = upk(acc[r]);
            A1f[base + r * 2] = fmaxf(v.x + v.y + bj, 0.f);
        }
    }
    __syncthreads();

    // ---- layer 2: 512 -> 256; thread j = tid&255, rows 8h..8h+7 (h = tid>>8) ----
    {
        int j = tid & 255;
        int rb = (tid >> 8) * 8;
        u64 acc[8];
        #pragma unroll
        for (int q = 0; q < 8; ++q) acc[q] = 0ULL;

        const u64* Wt = (const u64*)g_wt2;     // [kp*256 + j]
        #pragma unroll 4
        for (int kp = 0; kp < 256; ++kp) {
            u64 w2 = Wt[kp * 256 + j];         // LDG.64, coalesced
            const u64* ap0 = A1 + kp * PADR + rb;
            #pragma unroll
            for (int q = 0; q < 4; ++q) {
                ulonglong2 ap = *(const ulonglong2*)(ap0 + 2 * q);  // uniform LDS.128
                fma2(acc[2 * q],     ap.x, w2);
                fma2(acc[2 * q + 1], ap.y, w2);
            }
        }
        float bj = b2[j];
        float* B2f = (float*)B2;
        int base = ((j >> 1) * PADR + rb) * 2 + (j & 1);
        #pragma unroll
        for (int q = 0; q < 8; ++q) {
            float2 v = upk(acc[q]);
            B2f[base + q * 2] = fmaxf(v.x + v.y + bj, 0.f);
        }
    }
    __syncthreads();

    // ---- layer 3: 256 -> 128; thread j = tid&127, rows 4*rs..4*rs+3 (rs = tid>>7) ----
    {
        int j  = tid & 127;
        int rb = (tid >> 7) * 4;
        u64 acc[4];
        #pragma unroll
        for (int q = 0; q < 4; ++q) acc[q] = 0ULL;

        const u64* Wt = (const u64*)g_wt3;     // [kp*128 + j]
        #pragma unroll 4
        for (int kp = 0; kp < 128; ++kp) {
            u64 w2 = Wt[kp * 128 + j];         // LDG.64, coalesced
            const u64* bp0 = B2 + kp * PADR + rb;
            ulonglong2 a01 = *(const ulonglong2*)(bp0 + 0);   // uniform LDS.128
            ulonglong2 a23 = *(const ulonglong2*)(bp0 + 2);
            fma2(acc[0], a01.x, w2); fma2(acc[1], a01.y, w2);
            fma2(acc[2], a23.x, w2); fma2(acc[3], a23.y, w2);
        }
        __syncthreads();   // A1 reads (layer 2) complete; A3 overlay safe
        float bj = b3[j];
        #pragma unroll
        for (int q = 0; q < 4; ++q) {
            float2 v = upk(acc[q]);
            A3f[j * 16 + rb + q] = fmaxf(v.x + v.y + bj, 0.f);
        }
    }
    __syncthreads();

    // ---- layer 4: 128 -> 2 (one warp: r = tid>>1, jo = tid&1) ----
    if (tid < 32) {
        int r  = tid >> 1;             // 0..15
        int jo = tid & 1;
        float acc = b4[jo];
        #pragma unroll 8
        for (int k = 0; k < 128; ++k)
            acc += A3f[k * 16 + r] * W4[jo * 128 + k];
        out[(r0 + r) * 2 + jo] = acc;
    }
}

// ---------------- launch ----------------
extern "C" void kernel_launch(void* const* d_in, const int* in_sizes, int n_in,
                              void* d_out, int out_size) {
    const int*   x       = (const int*)  d_in[0];
    const int*   lengths = (const int*)  d_in[1];
    const float* emb     = (const float*)d_in[2];
    const float* W1      = (const float*)d_in[3];
    const float* b1      = (const float*)d_in[4];
    const float* W2      = (const float*)d_in[5];
    const float* b2      = (const float*)d_in[6];
    const float* W3      = (const float*)d_in[7];
    const float* b3      = (const float*)d_in[8];
    const float* W4      = (const float*)d_in[9];
    const float* b4      = (const float*)d_in[10];
    float* out = (float*)d_out;

    transpose_kernel<<<(229376 + 255) / 256, 256>>>(W1, W2, W3);
    mlp_kernel<<<N_BATCH / 16, 512>>>(x, lengths, emb, b1, b2, b3, W4, b4, out);
}